// round 8
// baseline (speedup 1.0000x reference)
#include <cuda_runtime.h>

#define NSLOPE 0.2f
#define NMAX   50048
#define EMAX   655360

// ---- device scratch (no runtime allocation allowed) ----
__device__ float g_h[NMAX * 128];     // h = in @ W
__device__ float g_y[NMAX * 128];     // layer output (input to next layer)
__device__ float g_o2[NMAX * 64];     // final pre-log-softmax
__device__ float g_as[NMAX];          // h . a_src per node
__device__ float g_ad[NMAX];          // h . a_dst per node
__device__ int   g_deg[NMAX];         // in-degree (w/o self loop)
__device__ int   g_start[NMAX];       // CSR segment start (by dst)
__device__ int   g_cur[NMAX];         // scatter cursors
__device__ int   g_csr[EMAX];         // src node per CSR slot
__device__ int   g_cnt;               // global slot allocator

typedef unsigned long long ull;

__device__ __forceinline__ ull ffma2(ull a, ull b, ull c) {
    ull d;
    asm("fma.rn.f32x2 %0, %1, %2, %3;" : "=l"(d) : "l"(a), "l"(b), "l"(c));
    return d;
}
__device__ __forceinline__ ull pack2(float x, float y) {
    ull r;
    asm("mov.b64 %0, {%1, %2};" : "=l"(r) : "f"(x), "f"(y));
    return r;
}
__device__ __forceinline__ void unpack2(ull v, float& lo, float& hi) {
    asm("mov.b64 {%0, %1}, %2;" : "=f"(lo), "=f"(hi) : "l"(v));
}

// ========================== CSR build (4 kernels) ==========================

__global__ void k_zero(int n) {
    int i = blockIdx.x * 256 + threadIdx.x;
    if (i < n) g_deg[i] = 0;
    if (i == 0) g_cnt = 0;
}

__global__ void k_count(const int* __restrict__ dst, int e) {
    int i = blockIdx.x * 256 + threadIdx.x;
    if (i < e) atomicAdd(&g_deg[dst[i]], 1);
}

// block-aggregated segment allocation + self-loop planting (replaces scan trio + k_self)
__global__ void k_alloc(int n) {
    __shared__ int s[256];
    __shared__ int base;
    int tid = threadIdx.x;
    int i = blockIdx.x * 256 + tid;
    int deg = (i < n) ? g_deg[i] + 1 : 0;  // +1 self loop
    s[tid] = deg;
    __syncthreads();
    for (int off = 1; off < 256; off <<= 1) {
        int a = s[tid];
        int b = (tid >= off) ? s[tid - off] : 0;
        __syncthreads();
        s[tid] = a + b;
        __syncthreads();
    }
    if (tid == 255) base = atomicAdd(&g_cnt, s[255]);
    __syncthreads();
    if (i < n) {
        int st = base + s[tid] - deg;
        g_start[i] = st;
        g_csr[st] = i;   // self-loop occupies slot 0
        g_cur[i] = 1;
    }
}

__global__ void k_scatter(const int* __restrict__ src, const int* __restrict__ dst, int e) {
    int i = blockIdx.x * 256 + threadIdx.x;
    if (i < e) {
        int d = dst[i];
        int p = atomicAdd(&g_cur[d], 1);
        g_csr[g_start[d] + p] = src[i];
    }
}

// ================= GEMM (f32x2 packed) + fused attention dots =================
// A: [M,128] row-major, W: [128,BN] row-major, H: [M,BN]
// Block: 256 threads, tile 128 x BN. Each thread: RPT rows x 8 cols (4 f32x2).
// Epilogue: lanes owning one row warp-reduce h.a_src / h.a_dst.

template <int BN>
__global__ __launch_bounds__(256) void k_gemm(
    const float* __restrict__ A, const float* __restrict__ W,
    float* __restrict__ H, const float* __restrict__ a_s,
    const float* __restrict__ a_d, int M)
{
    constexpr int TX  = BN / 8;      // threads across cols (16 or 8)
    constexpr int TY  = 256 / TX;    // row groups (16 or 32)
    constexpr int RPT = 128 / TY;    // rows per thread (8 or 4)
    __shared__ ull Xs2[128][8];      // A tile, each entry duplicated (a,a)
    __shared__ ull Ws2[8][BN / 2];   // W tile as (w0,w1) pairs

    int tid = threadIdx.x;
    int tx = tid % TX, ty = tid / TX;
    int lane = tid & 31;
    int row0 = blockIdx.x * 128;

    ull acc[RPT][4];
#pragma unroll
    for (int j = 0; j < RPT; j++)
#pragma unroll
        for (int c = 0; c < 4; c++) acc[j][c] = 0ull;

    for (int k0 = 0; k0 < 128; k0 += 8) {
        // fill X tile: 128 rows x 8 k = 256 float4; one float4 per thread, duplicated
        {
            int r = tid >> 1, half = tid & 1;
            int gr = row0 + r;
            float4 av = make_float4(0.f, 0.f, 0.f, 0.f);
            if (gr < M) av = *(const float4*)(A + (size_t)gr * 128 + k0 + half * 4);
            ull* xp = &Xs2[r][half * 4];
            xp[0] = pack2(av.x, av.x);
            xp[1] = pack2(av.y, av.y);
            xp[2] = pack2(av.z, av.z);
            xp[3] = pack2(av.w, av.w);
        }
        // fill W tile: 8 k-rows x BN cols = 2*BN float4
        if (tid < 2 * BN) {
            int kr = tid / (BN / 4), c4 = tid % (BN / 4);
            float4 wv = *(const float4*)(W + (size_t)(k0 + kr) * BN + c4 * 4);
            *(float4*)&Ws2[kr][c4 * 2] = wv;
        }
        __syncthreads();
#pragma unroll
        for (int kk = 0; kk < 8; kk++) {
            ulonglong2 w0 = *(ulonglong2*)&Ws2[kk][tx * 4];
            ulonglong2 w1 = *(ulonglong2*)&Ws2[kk][tx * 4 + 2];
#pragma unroll
            for (int j = 0; j < RPT; j++) {
                ull a = Xs2[ty + j * TY][kk];
                acc[j][0] = ffma2(a, w0.x, acc[j][0]);
                acc[j][1] = ffma2(a, w0.y, acc[j][1]);
                acc[j][2] = ffma2(a, w1.x, acc[j][2]);
                acc[j][3] = ffma2(a, w1.y, acc[j][3]);
            }
        }
        __syncthreads();
    }

    // attention vectors for the 8 cols this thread owns
    float asv[8], adv[8];
#pragma unroll
    for (int c = 0; c < 8; c++) {
        asv[c] = a_s[tx * 8 + c];
        adv[c] = a_d[tx * 8 + c];
    }

#pragma unroll
    for (int j = 0; j < RPT; j++) {
        int r = row0 + ty + j * TY;
        float o[8];
        unpack2(acc[j][0], o[0], o[1]);
        unpack2(acc[j][1], o[2], o[3]);
        unpack2(acc[j][2], o[4], o[5]);
        unpack2(acc[j][3], o[6], o[7]);
        if (r < M) {
            *(float4*)(H + (size_t)r * BN + tx * 8)     = make_float4(o[0], o[1], o[2], o[3]);
            *(float4*)(H + (size_t)r * BN + tx * 8 + 4) = make_float4(o[4], o[5], o[6], o[7]);
        }
        float sa = 0.f, sd = 0.f;
#pragma unroll
        for (int c = 0; c < 8; c++) {
            sa += o[c] * asv[c];
            sd += o[c] * adv[c];
        }
#pragma unroll
        for (int off = TX / 2; off; off >>= 1) {
            sa += __shfl_xor_sync(0xffffffffu, sa, off);
            sd += __shfl_xor_sync(0xffffffffu, sd, off);
        }
        if ((lane & (TX - 1)) == 0 && r < M) {
            g_as[r] = sa;
            g_ad[r] = sd;
        }
    }
}

// ============ warp-per-dst-node segment softmax + weighted gather ============

template <int D, bool SILU>
__global__ void k_agg(const float* __restrict__ h, const float* __restrict__ bias,
                      float* __restrict__ out, int n) {
    constexpr int MAXDEG = 128;
    constexpr int FP = D / 32;  // floats per lane (4 or 2)
    __shared__ float wsh[8][MAXDEG];
    __shared__ int ssh[8][MAXDEG];
    int warp = threadIdx.x >> 5, lane = threadIdx.x & 31;
    int d = blockIdx.x * 8 + warp;
    if (d >= n) return;
    int st = g_start[d];
    int deg = g_deg[d] + 1;
    float ad = g_ad[d];
    int f = lane * FP;
    float acc[FP];
#pragma unroll
    for (int j = 0; j < FP; j++) acc[j] = 0.f;
    float inv;

    if (deg <= MAXDEG) {
        // phase 1: lanes parallel over neighbors — alpha, max, exp, denom
        float m = -1e30f;
        for (int i = lane; i < deg; i += 32) {
            int s = g_csr[st + i];
            ssh[warp][i] = s;
            float al = g_as[s] + ad;
            al = al > 0.f ? al : NSLOPE * al;
            wsh[warp][i] = al;
            m = fmaxf(m, al);
        }
#pragma unroll
        for (int o = 16; o; o >>= 1) m = fmaxf(m, __shfl_xor_sync(0xffffffffu, m, o));
        __syncwarp();
        float den = 0.f;
        for (int i = lane; i < deg; i += 32) {
            float w = __expf(wsh[warp][i] - m);
            wsh[warp][i] = w;
            den += w;
        }
#pragma unroll
        for (int o = 16; o; o >>= 1) den += __shfl_xor_sync(0xffffffffu, den, o);
        __syncwarp();
        inv = 1.f / den;
        // phase 2: warp gathers neighbor h rows (coalesced, L2-resident), 2x unroll
        int i = 0;
        for (; i + 2 <= deg; i += 2) {
            int s0 = ssh[warp][i];
            int s1 = ssh[warp][i + 1];
            float c0 = wsh[warp][i];
            float c1 = wsh[warp][i + 1];
            const float* h0 = h + (size_t)s0 * D + f;
            const float* h1 = h + (size_t)s1 * D + f;
            if constexpr (FP == 4) {
                float4 v0 = *(const float4*)h0;
                float4 v1 = *(const float4*)h1;
                acc[0] += c0 * v0.x + c1 * v1.x;
                acc[1] += c0 * v0.y + c1 * v1.y;
                acc[2] += c0 * v0.z + c1 * v1.z;
                acc[3] += c0 * v0.w + c1 * v1.w;
            } else {
                float2 v0 = *(const float2*)h0;
                float2 v1 = *(const float2*)h1;
                acc[0] += c0 * v0.x + c1 * v1.x;
                acc[1] += c0 * v0.y + c1 * v1.y;
            }
        }
        if (i < deg) {
            int s0 = ssh[warp][i];
            float c0 = wsh[warp][i];
            const float* h0 = h + (size_t)s0 * D + f;
            if constexpr (FP == 4) {
                float4 v0 = *(const float4*)h0;
                acc[0] += c0 * v0.x;
                acc[1] += c0 * v0.y;
                acc[2] += c0 * v0.z;
                acc[3] += c0 * v0.w;
            } else {
                float2 v0 = *(const float2*)h0;
                acc[0] += c0 * v0.x;
                acc[1] += c0 * v0.y;
            }
        }
    } else {
        // fallback: online softmax (never expected at these degrees)
        float m = -1e30f, den = 0.f;
        for (int i = 0; i < deg; i++) {
            int s = g_csr[st + i];
            float al = g_as[s] + ad;
            al = al > 0.f ? al : NSLOPE * al;
            float nm = fmaxf(m, al);
            float sc = __expf(m - nm);
            float w = __expf(al - nm);
            den = den * sc + w;
            const float* hp = h + (size_t)s * D + f;
#pragma unroll
            for (int j = 0; j < FP; j++) acc[j] = acc[j] * sc + w * hp[j];
            m = nm;
        }
        inv = 1.f / den;
    }

#pragma unroll
    for (int j = 0; j < FP; j++) {
        float v = acc[j] * inv + bias[f + j];
        if (SILU) v = v / (1.f + __expf(-v));
        out[(size_t)d * D + f + j] = v;
    }
}

// ========================== log_softmax over 64 cols ==========================

__global__ void k_lsm(const float* __restrict__ in, float* __restrict__ out, int n) {
    int warp = threadIdx.x >> 5, lane = threadIdx.x & 31;
    int r = blockIdx.x * 8 + warp;
    if (r >= n) return;
    float2 v = *(const float2*)&in[(size_t)r * 64 + lane * 2];
    float m = fmaxf(v.x, v.y);
#pragma unroll
    for (int o = 16; o; o >>= 1) m = fmaxf(m, __shfl_xor_sync(0xffffffffu, m, o));
    float s = __expf(v.x - m) + __expf(v.y - m);
#pragma unroll
    for (int o = 16; o; o >>= 1) s += __shfl_xor_sync(0xffffffffu, s, o);
    float l = m + __logf(s);
    float2 o2 = make_float2(v.x - l, v.y - l);
    *(float2*)&out[(size_t)r * 64 + lane * 2] = o2;
}

// ========================== host launcher ==========================

extern "C" void kernel_launch(void* const* d_in, const int* in_sizes, int n_in,
                              void* d_out, int out_size) {
    const float* x   = (const float*)d_in[0];
    const int*   ei  = (const int*)d_in[1];
    const float* W0  = (const float*)d_in[2];
    const float* as0 = (const float*)d_in[3];
    const float* ad0 = (const float*)d_in[4];
    const float* b0  = (const float*)d_in[5];
    const float* W1  = (const float*)d_in[6];
    const float* as1 = (const float*)d_in[7];
    const float* ad1 = (const float*)d_in[8];
    const float* b1  = (const float*)d_in[9];
    const float* W2  = (const float*)d_in[10];
    const float* as2 = (const float*)d_in[11];
    const float* ad2 = (const float*)d_in[12];
    const float* b2  = (const float*)d_in[13];

    int n = in_sizes[0] / 128;  // 50000
    int e = in_sizes[1] / 2;    // 600000
    const int* src = ei;
    const int* dst = ei + e;
    float* outp = (float*)d_out;

    float *ph, *py, *po2;
    cudaGetSymbolAddress((void**)&ph, g_h);
    cudaGetSymbolAddress((void**)&py, g_y);
    cudaGetSymbolAddress((void**)&po2, g_o2);

    int nbN = (n + 255) / 256;
    int nbE = (e + 255) / 256;
    int nbG = (n + 127) / 128;
    int nbA = (n + 7) / 8;
    int nbW = (n + 7) / 8;

    // CSR by dst (includes self-loops at segment head)
    k_zero<<<nbN, 256>>>(n);
    k_count<<<nbE, 256>>>(dst, e);
    k_alloc<<<nbN, 256>>>(n);
    k_scatter<<<nbE, 256>>>(src, dst, e);

    // layer 0: 128 -> 128, SiLU
    k_gemm<128><<<nbG, 256>>>(x, W0, ph, as0, ad0, n);
    k_agg<128, true><<<nbA, 256>>>(ph, b0, py, n);

    // layer 1: 128 -> 128, SiLU
    k_gemm<128><<<nbG, 256>>>(py, W1, ph, as1, ad1, n);
    k_agg<128, true><<<nbA, 256>>>(ph, b1, py, n);

    // layer 2: 128 -> 64, no SiLU, then log_softmax
    k_gemm<64><<<nbG, 256>>>(py, W2, ph, as2, ad2, n);
    k_agg<64, false><<<nbA, 256>>>(ph, b2, po2, n);
    k_lsm<<<nbW, 256>>>(po2, outp, n);
}

// round 9
// speedup vs baseline: 1.9275x; 1.9275x over previous
#include <cuda_runtime.h>

#define NSLOPE 0.2f
#define NMAX   50048
#define EMAX   655360

// ---- device scratch (no runtime allocation allowed) ----
__device__ float g_h[NMAX * 128];     // h = in @ W
__device__ float g_y[NMAX * 128];     // layer output (input to next layer)
__device__ float g_o2[NMAX * 64];     // final pre-log-softmax
__device__ float g_as[NMAX];          // h . a_src per node
__device__ float g_ad[NMAX];          // h . a_dst per node
__device__ int   g_deg[NMAX];         // in-degree (w/o self loop)
__device__ int   g_start[NMAX];       // CSR segment start (by dst)
__device__ int   g_cur[NMAX];         // scatter cursors
__device__ int   g_csr[EMAX];         // src node per CSR slot
__device__ int   g_cnt;               // global slot allocator

// ========================== CSR build (4 kernels) ==========================

__global__ void k_zero(int n) {
    int i = blockIdx.x * 256 + threadIdx.x;
    if (i < n) g_deg[i] = 0;
    if (i == 0) g_cnt = 0;
}

__global__ void k_count(const int* __restrict__ dst, int e) {
    int i = blockIdx.x * 256 + threadIdx.x;
    if (i < e) atomicAdd(&g_deg[dst[i]], 1);
}

// block-aggregated segment allocation + self-loop planting
__global__ void k_alloc(int n) {
    __shared__ int s[256];
    __shared__ int base;
    int tid = threadIdx.x;
    int i = blockIdx.x * 256 + tid;
    int deg = (i < n) ? g_deg[i] + 1 : 0;  // +1 self loop
    s[tid] = deg;
    __syncthreads();
    for (int off = 1; off < 256; off <<= 1) {
        int a = s[tid];
        int b = (tid >= off) ? s[tid - off] : 0;
        __syncthreads();
        s[tid] = a + b;
        __syncthreads();
    }
    if (tid == 255) base = atomicAdd(&g_cnt, s[255]);
    __syncthreads();
    if (i < n) {
        int st = base + s[tid] - deg;
        g_start[i] = st;
        g_csr[st] = i;   // self-loop occupies slot 0
        g_cur[i] = 1;
    }
}

__global__ void k_scatter(const int* __restrict__ src, const int* __restrict__ dst, int e) {
    int i = blockIdx.x * 256 + threadIdx.x;
    if (i < e) {
        int d = dst[i];
        int p = atomicAdd(&g_cur[d], 1);
        g_csr[g_start[d] + p] = src[i];
    }
}

// ============== GEMM (scalar FFMA) + fused attention dots ==============
// A: [M,128] row-major, W: [128,BN] row-major, H: [M,BN]
// Block 256 threads, tile 64 x BN, BK=16. Thread: RPT rows x 4 cols.
// Epilogue: lanes owning one row reduce h.a_src / h.a_dst via shfl.

template <int BN>
__global__ __launch_bounds__(256) void k_gemm(
    const float* __restrict__ A, const float* __restrict__ W,
    float* __restrict__ H, const float* __restrict__ a_s,
    const float* __restrict__ a_d, int M)
{
    constexpr int TX  = BN / 4;    // threads across cols (32 or 16)
    constexpr int TY  = 256 / TX;  // row groups (8 or 16)
    constexpr int RPT = 64 / TY;   // rows per thread (8 or 4)
    __shared__ float Xs[64][16];
    __shared__ float Ws[16][BN];

    int tid = threadIdx.x;
    int tx = tid % TX, ty = tid / TX;
    int lane = tid & 31;
    int row0 = blockIdx.x * 64;

    float acc[RPT][4];
#pragma unroll
    for (int j = 0; j < RPT; j++) {
        acc[j][0] = acc[j][1] = acc[j][2] = acc[j][3] = 0.f;
    }

    for (int k0 = 0; k0 < 128; k0 += 16) {
        // X tile: 64 rows x 16 k = 1024 floats, one float4 per thread
        {
            int r = tid >> 2, kk = (tid & 3) * 4;
            int gr = row0 + r;
            float4 v = make_float4(0.f, 0.f, 0.f, 0.f);
            if (gr < M) v = *(const float4*)(A + (size_t)gr * 128 + k0 + kk);
            *(float4*)&Xs[r][kk] = v;
        }
        // W tile: 16 x BN floats
#pragma unroll
        for (int t = 0; t < BN / 64; t++) {
            int idx = (tid + t * 256) * 4;
            int kr = idx / BN, c = idx % BN;
            *(float4*)&Ws[kr][c] = *(const float4*)(W + (size_t)(k0 + kr) * BN + c);
        }
        __syncthreads();
#pragma unroll
        for (int kk = 0; kk < 16; kk++) {
            float4 w = *(const float4*)&Ws[kk][tx * 4];
#pragma unroll
            for (int j = 0; j < RPT; j++) {
                float a = Xs[ty + j * TY][kk];
                acc[j][0] += a * w.x;
                acc[j][1] += a * w.y;
                acc[j][2] += a * w.z;
                acc[j][3] += a * w.w;
            }
        }
        __syncthreads();
    }

    float asv[4], adv[4];
#pragma unroll
    for (int c = 0; c < 4; c++) {
        asv[c] = a_s[tx * 4 + c];
        adv[c] = a_d[tx * 4 + c];
    }

#pragma unroll
    for (int j = 0; j < RPT; j++) {
        int r = row0 + ty + j * TY;
        if (r < M) {
            *(float4*)(H + (size_t)r * BN + tx * 4) =
                make_float4(acc[j][0], acc[j][1], acc[j][2], acc[j][3]);
        }
        float sa = acc[j][0] * asv[0] + acc[j][1] * asv[1] +
                   acc[j][2] * asv[2] + acc[j][3] * asv[3];
        float sd = acc[j][0] * adv[0] + acc[j][1] * adv[1] +
                   acc[j][2] * adv[2] + acc[j][3] * adv[3];
#pragma unroll
        for (int off = TX / 2; off; off >>= 1) {
            sa += __shfl_xor_sync(0xffffffffu, sa, off);
            sd += __shfl_xor_sync(0xffffffffu, sd, off);
        }
        if ((lane & (TX - 1)) == 0 && r < M) {
            g_as[r] = sa;
            g_ad[r] = sd;
        }
    }
}

// ============ warp-per-dst-node segment softmax + weighted gather ============

template <int D, bool SILU>
__global__ void k_agg(const float* __restrict__ h, const float* __restrict__ bias,
                      float* __restrict__ out, int n) {
    constexpr int MAXDEG = 128;
    constexpr int FP = D / 32;  // floats per lane (4 or 2)
    __shared__ float wsh[8][MAXDEG];
    __shared__ int ssh[8][MAXDEG];
    int warp = threadIdx.x >> 5, lane = threadIdx.x & 31;
    int d = blockIdx.x * 8 + warp;
    if (d >= n) return;
    int st = g_start[d];
    int deg = g_deg[d] + 1;
    float ad = g_ad[d];
    int f = lane * FP;
    float acc[FP];
#pragma unroll
    for (int j = 0; j < FP; j++) acc[j] = 0.f;
    float inv;

    if (deg <= MAXDEG) {
        // phase 1: lanes parallel over neighbors — alpha, max, exp, denom
        float m = -1e30f;
        for (int i = lane; i < deg; i += 32) {
            int s = g_csr[st + i];
            ssh[warp][i] = s;
            float al = g_as[s] + ad;
            al = al > 0.f ? al : NSLOPE * al;
            wsh[warp][i] = al;
            m = fmaxf(m, al);
        }
#pragma unroll
        for (int o = 16; o; o >>= 1) m = fmaxf(m, __shfl_xor_sync(0xffffffffu, m, o));
        __syncwarp();
        float den = 0.f;
        for (int i = lane; i < deg; i += 32) {
            float w = __expf(wsh[warp][i] - m);
            wsh[warp][i] = w;
            den += w;
        }
#pragma unroll
        for (int o = 16; o; o >>= 1) den += __shfl_xor_sync(0xffffffffu, den, o);
        __syncwarp();
        inv = 1.f / den;
        // phase 2: warp gathers neighbor h rows (coalesced, L2-resident), 2x unroll
        int i = 0;
        for (; i + 2 <= deg; i += 2) {
            int s0 = ssh[warp][i];
            int s1 = ssh[warp][i + 1];
            float c0 = wsh[warp][i];
            float c1 = wsh[warp][i + 1];
            const float* h0 = h + (size_t)s0 * D + f;
            const float* h1 = h + (size_t)s1 * D + f;
            if constexpr (FP == 4) {
                float4 v0 = *(const float4*)h0;
                float4 v1 = *(const float4*)h1;
                acc[0] += c0 * v0.x + c1 * v1.x;
                acc[1] += c0 * v0.y + c1 * v1.y;
                acc[2] += c0 * v0.z + c1 * v1.z;
                acc[3] += c0 * v0.w + c1 * v1.w;
            } else {
                float2 v0 = *(const float2*)h0;
                float2 v1 = *(const float2*)h1;
                acc[0] += c0 * v0.x + c1 * v1.x;
                acc[1] += c0 * v0.y + c1 * v1.y;
            }
        }
        if (i < deg) {
            int s0 = ssh[warp][i];
            float c0 = wsh[warp][i];
            const float* h0 = h + (size_t)s0 * D + f;
            if constexpr (FP == 4) {
                float4 v0 = *(const float4*)h0;
                acc[0] += c0 * v0.x;
                acc[1] += c0 * v0.y;
                acc[2] += c0 * v0.z;
                acc[3] += c0 * v0.w;
            } else {
                float2 v0 = *(const float2*)h0;
                acc[0] += c0 * v0.x;
                acc[1] += c0 * v0.y;
            }
        }
    } else {
        // fallback: online softmax (never expected at these degrees)
        float m = -1e30f, den = 0.f;
        for (int i = 0; i < deg; i++) {
            int s = g_csr[st + i];
            float al = g_as[s] + ad;
            al = al > 0.f ? al : NSLOPE * al;
            float nm = fmaxf(m, al);
            float sc = __expf(m - nm);
            float w = __expf(al - nm);
            den = den * sc + w;
            const float* hp = h + (size_t)s * D + f;
#pragma unroll
            for (int j = 0; j < FP; j++) acc[j] = acc[j] * sc + w * hp[j];
            m = nm;
        }
        inv = 1.f / den;
    }

#pragma unroll
    for (int j = 0; j < FP; j++) {
        float v = acc[j] * inv + bias[f + j];
        if (SILU) v = v / (1.f + __expf(-v));
        out[(size_t)d * D + f + j] = v;
    }
}

// ========================== log_softmax over 64 cols ==========================

__global__ void k_lsm(const float* __restrict__ in, float* __restrict__ out, int n) {
    int warp = threadIdx.x >> 5, lane = threadIdx.x & 31;
    int r = blockIdx.x * 8 + warp;
    if (r >= n) return;
    float2 v = *(const float2*)&in[(size_t)r * 64 + lane * 2];
    float m = fmaxf(v.x, v.y);
#pragma unroll
    for (int o = 16; o; o >>= 1) m = fmaxf(m, __shfl_xor_sync(0xffffffffu, m, o));
    float s = __expf(v.x - m) + __expf(v.y - m);
#pragma unroll
    for (int o = 16; o; o >>= 1) s += __shfl_xor_sync(0xffffffffu, s, o);
    float l = m + __logf(s);
    float2 o2 = make_float2(v.x - l, v.y - l);
    *(float2*)&out[(size_t)r * 64 + lane * 2] = o2;
}

// ========================== host launcher ==========================

extern "C" void kernel_launch(void* const* d_in, const int* in_sizes, int n_in,
                              void* d_out, int out_size) {
    const float* x   = (const float*)d_in[0];
    const int*   ei  = (const int*)d_in[1];
    const float* W0  = (const float*)d_in[2];
    const float* as0 = (const float*)d_in[3];
    const float* ad0 = (const float*)d_in[4];
    const float* b0  = (const float*)d_in[5];
    const float* W1  = (const float*)d_in[6];
    const float* as1 = (const float*)d_in[7];
    const float* ad1 = (const float*)d_in[8];
    const float* b1  = (const float*)d_in[9];
    const float* W2  = (const float*)d_in[10];
    const float* as2 = (const float*)d_in[11];
    const float* ad2 = (const float*)d_in[12];
    const float* b2  = (const float*)d_in[13];

    int n = in_sizes[0] / 128;  // 50000
    int e = in_sizes[1] / 2;    // 600000
    const int* src = ei;
    const int* dst = ei + e;
    float* outp = (float*)d_out;

    float *ph, *py, *po2;
    cudaGetSymbolAddress((void**)&ph, g_h);
    cudaGetSymbolAddress((void**)&py, g_y);
    cudaGetSymbolAddress((void**)&po2, g_o2);

    int nbN = (n + 255) / 256;
    int nbE = (e + 255) / 256;
    int nbG = (n + 63) / 64;
    int nbA = (n + 7) / 8;
    int nbW = (n + 7) / 8;

    // CSR by dst (includes self-loops at segment head)
    k_zero<<<nbN, 256>>>(n);
    k_count<<<nbE, 256>>>(dst, e);
    k_alloc<<<nbN, 256>>>(n);
    k_scatter<<<nbE, 256>>>(src, dst, e);

    // layer 0: 128 -> 128, SiLU
    k_gemm<128><<<nbG, 256>>>(x, W0, ph, as0, ad0, n);
    k_agg<128, true><<<nbA, 256>>>(ph, b0, py, n);

    // layer 1: 128 -> 128, SiLU
    k_gemm<128><<<nbG, 256>>>(py, W1, ph, as1, ad1, n);
    k_agg<128, true><<<nbA, 256>>>(ph, b1, py, n);

    // layer 2: 128 -> 64, no SiLU, then log_softmax
    k_gemm<64><<<nbG, 256>>>(py, W2, ph, as2, ad2, n);
    k_agg<64, false><<<nbA, 256>>>(ph, b2, po2, n);
    k_lsm<<<nbW, 256>>>(po2, outp, n);
}